// round 13
// baseline (speedup 1.0000x reference)
#include <cuda_runtime.h>

// GRU_67714454389230: 2-layer GRU (H=12, IN=18) + fc(12->1), B=4096, T=512.
// Round 13: the untested config — ONE batch per 16-lane group with ALL
// recurrent weights in registers (R11 failed only because w_hh1 was in smem).
// 2048 single-warp blocks -> ~12/SM (launch_bounds(32,12), 170-reg target),
// ~2.8 warps/SMSP: half the per-warp work, ~1.7x the latency hiding.
// Keeps: R7 plane-float4 gi + R7 gi0, R8 layer-pipelining + combined
// exchange, R9 r/z pre-scaling (sigmoid = fma(tanh, .5, .5)).

static constexpr int IN_DIM = 18;
static constexpr int HID    = 12;
static constexpr int BATCH  = 4096;
static constexpr int SEQ    = 512;
static constexpr size_t NROWS = (size_t)BATCH * SEQ;   // 2,097,152

typedef unsigned long long ull;

// plane layout: g_gi0[u*NROWS + (b*SEQ+t)] = float4(0.5*gi_r, 0.5*gi_z, gi_n, 0)
__device__ float4 g_gi0[HID * NROWS];

// ---------------- helpers ----------------
__device__ __forceinline__ ull ffma2(ull a, ull b, ull c) {
    ull d;
    asm("fma.rn.f32x2 %0, %1, %2, %3;" : "=l"(d) : "l"(a), "l"(b), "l"(c));
    return d;
}
__device__ __forceinline__ float f2sum(ull v) {
    float lo, hi;
    asm("mov.b64 {%0, %1}, %2;" : "=f"(lo), "=f"(hi) : "l"(v));
    return lo + hi;
}
__device__ __forceinline__ ull fpack(float lo, float hi) {
    ull v;
    asm("mov.b64 %0, {%1, %2};" : "=l"(v) : "f"(lo), "f"(hi));
    return v;
}
__device__ __forceinline__ float tanhapx(float x) {
    float y;
    asm("tanh.approx.f32 %0, %1;" : "=f"(y) : "f"(x));
    return y;
}
// input is ALREADY 0.5*(pre-activation)
__device__ __forceinline__ float sig_pre(float half_x) {
    return fmaf(tanhapx(half_x), 0.5f, 0.5f);
}

// ---------------- kernel 1: gi0 (R7 version + 0.5 pre-scale on r,z) --------
static constexpr int GI_ROWS = 512;

__global__ __launch_bounds__(128, 4)
void gi0_kernel(const float* __restrict__ x,
                const float* __restrict__ w_ih0,
                const float* __restrict__ b_ih0)
{
    __shared__ ull   s_xu[GI_ROWS * 11];   // 9 pairs + pad to 11 -> conflict-free
    __shared__ ull   s_w[36][9];
    __shared__ float s_b[36];

    const int tid = threadIdx.x;
    for (int i = tid; i < 36 * 9; i += 128) {
        const int j = i / 9, k = i % 9;
        const float s = (j < 24) ? 0.5f : 1.0f;     // r,z rows scaled
        const float* wp = w_ih0 + j * IN_DIM + 2 * k;
        s_w[j][k] = fpack(wp[0] * s, wp[1] * s);
    }
    if (tid < 36) s_b[tid] = b_ih0[tid] * ((tid < 24) ? 0.5f : 1.0f);

    const size_t row0 = (size_t)blockIdx.x * GI_ROWS;
    const ull* xg = (const ull*)(x + row0 * IN_DIM);
    for (int i = tid; i < GI_ROWS * 9; i += 128) {
        const int r = i / 9, p = i % 9;
        s_xu[r * 11 + p] = xg[i];
    }
    __syncthreads();

    ull xp[4][9];
#pragma unroll
    for (int j = 0; j < 4; ++j) {
        const ull* row = s_xu + (tid + j * 128) * 11;
#pragma unroll
        for (int k = 0; k < 9; ++k) xp[j][k] = row[k];
    }

#pragma unroll
    for (int u = 0; u < HID; ++u) {
        float res[4][3];
#pragma unroll
        for (int g = 0; g < 3; ++g) {
            const int jrow = g * HID + u;
            ull w[9];
#pragma unroll
            for (int k = 0; k < 9; ++k) w[k] = s_w[jrow][k];
            const float b = s_b[jrow];
#pragma unroll
            for (int j = 0; j < 4; ++j) {
                ull acc = fpack(b, 0.0f);
#pragma unroll
                for (int k = 0; k < 9; ++k) acc = ffma2(xp[j][k], w[k], acc);
                res[j][g] = f2sum(acc);
            }
        }
        float4* plane = g_gi0 + (size_t)u * NROWS + row0;
#pragma unroll
        for (int j = 0; j < 4; ++j)
            plane[tid + j * 128] = make_float4(res[j][0], res[j][1], res[j][2], 0.0f);
    }
}

// ---------------- kernel 2: recurrent scan ----------------
// 2048 single-warp blocks; warp = 2 groups of 16 lanes, ONE batch per group.
// ALL recurrent weights in registers.
static constexpr int S_THREADS = 32;
static constexpr int S_GRID    = BATCH / 2;   // 2048 blocks

__global__ __launch_bounds__(S_THREADS, 12)
void gru_scan_kernel(const float* __restrict__ w_hh0, const float* __restrict__ b_hh0,
                     const float* __restrict__ w_ih1, const float* __restrict__ w_hh1,
                     const float* __restrict__ b_ih1, const float* __restrict__ b_hh1,
                     const float* __restrict__ fc_w, const float* __restrict__ fc_b,
                     float* __restrict__ out)
{
    __shared__ __align__(16) float s_h1[2][HID];      // [group][unit]
    __shared__ __align__(16) float s_h2[2][HID];
    __shared__ float s_fcw[HID];

    const int tid   = threadIdx.x;
    const int grp_l = tid >> 4;
    const int sub   = tid & 15;
    const int u     = (sub < HID) ? sub : HID - 1;
    const int batch = blockIdx.x * 2 + grp_l;

    if (tid < HID) s_fcw[tid] = fc_w[tid];

    // ALL recurrent weights in registers (f32x2 pairs); r,z rows scaled 0.5.
    ull whh0[3][6], wih1[3][6], whh1[3][6];
#pragma unroll
    for (int g = 0; g < 3; ++g) {
        const float s = (g < 2) ? 0.5f : 1.0f;
        const float* p0 = w_hh0 + (g * HID + u) * HID;
        const float* p1 = w_ih1 + (g * HID + u) * HID;
        const float* p2 = w_hh1 + (g * HID + u) * HID;
#pragma unroll
        for (int i = 0; i < 6; ++i) {
            whh0[g][i] = fpack(p0[2*i] * s, p0[2*i+1] * s);
            wih1[g][i] = fpack(p1[2*i] * s, p1[2*i+1] * s);
            whh1[g][i] = fpack(p2[2*i] * s, p2[2*i+1] * s);
        }
    }

    const float bh0r = b_hh0[u] * 0.5f;
    const float bh0z = b_hh0[HID + u] * 0.5f;
    const float bh0n = b_hh0[2 * HID + u];
    const ull pbh0n = fpack(bh0n, 0.0f);
    const ull pb2r  = fpack((b_ih1[u]       + b_hh1[u])       * 0.5f, 0.0f);
    const ull pb2z  = fpack((b_ih1[HID + u] + b_hh1[HID + u]) * 0.5f, 0.0f);
    const ull pb2in = fpack(b_ih1[2 * HID + u], 0.0f);
    const ull pb2hn = fpack(b_hh1[2 * HID + u], 0.0f);
    const float fcb = fc_b[0];

    // plane gi pointer: per-lane contiguous stream (16B/step -> L1-hit heavy)
    const float4* gp = g_gi0 + (size_t)u * NROWS + (size_t)batch * SEQ;

    ull H1[6], H2[6];
#pragma unroll
    for (int i = 0; i < 6; ++i) { H1[i] = H2[i] = 0ull; }
    float hp1, hp2 = 0.0f;
    __syncwarp();

    // ---- prologue: h1[0] = GRU1(gi0[0], 0) ----
    {
        const float4 g0 = gp[0];
        const float r = sig_pre(g0.x + bh0r);
        const float z = sig_pre(g0.y + bh0z);
        const float n = tanhapx(fmaf(r, bh0n, g0.z));
        hp1 = n - z * n;
        if (sub < HID) s_h1[grp_l][u] = hp1;
        __syncwarp();
        const ulonglong2* pa = (const ulonglong2*)s_h1[grp_l];
        const ulonglong2 a0 = pa[0], a1 = pa[1], a2 = pa[2];
        H1[0] = a0.x; H1[1] = a0.y; H1[2] = a1.x;
        H1[3] = a1.y; H1[4] = a2.x; H1[5] = a2.y;
    }

    float4 gc = gp[1];   // gi for t+1 = 1

#pragma unroll 1
    for (int t = 0; t < SEQ; ++t) {
        const int tn = (t + 2 < SEQ) ? (t + 2) : SEQ - 1;
        const float4 gn = gp[tn];

        // ======== layer 2 @ t (H1=h1[t], H2=h2[t-1])  +  layer 1 @ t+1 ========
        ull pr = pb2r, pz = pb2z, pn = pb2hn, pi = pb2in;
        ull qr = fpack(gc.x, bh0r), qz = fpack(gc.y, bh0z), qn = pbh0n;

#pragma unroll
        for (int i = 0; i < 6; ++i) {
            pr = ffma2(H2[i], whh1[0][i], pr);
            pz = ffma2(H2[i], whh1[1][i], pz);
            pn = ffma2(H2[i], whh1[2][i], pn);
            pr = ffma2(H1[i], wih1[0][i], pr);
            pz = ffma2(H1[i], wih1[1][i], pz);
            pi = ffma2(H1[i], wih1[2][i], pi);
            qr = ffma2(H1[i], whh0[0][i], qr);
            qz = ffma2(H1[i], whh0[1][i], qz);
            qn = ffma2(H1[i], whh0[2][i], qn);
        }

        // layer2 activations -> h2[t]
        const float r2 = sig_pre(f2sum(pr));
        const float z2 = sig_pre(f2sum(pz));
        const float n2 = tanhapx(fmaf(r2, f2sum(pn), f2sum(pi)));
        const float hn2 = fmaf(z2, hp2 - n2, n2);
        hp2 = hn2;

        // layer1 activations -> h1[t+1]
        const float r1 = sig_pre(f2sum(qr));
        const float z1 = sig_pre(f2sum(qz));
        const float n1 = tanhapx(fmaf(r1, f2sum(qn), gc.z));
        const float hn1 = fmaf(z1, hp1 - n1, n1);
        hp1 = hn1;

        // ======== combined exchange ========
        if (sub < HID) {
            s_h1[grp_l][u] = hn1;
            s_h2[grp_l][u] = hn2;
        }
        __syncwarp();
        {
            const ulonglong2* pa = (const ulonglong2*)s_h1[grp_l];
            const ulonglong2 a0 = pa[0], a1 = pa[1], a2 = pa[2];
            H1[0] = a0.x; H1[1] = a0.y; H1[2] = a1.x;
            H1[3] = a1.y; H1[4] = a2.x; H1[5] = a2.y;
        }
        {
            const ulonglong2* pa = (const ulonglong2*)s_h2[grp_l];
            const ulonglong2 a0 = pa[0], a1 = pa[1], a2 = pa[2];
            H2[0] = a0.x; H2[1] = a0.y; H2[2] = a1.x;
            H2[3] = a1.y; H2[4] = a2.x; H2[5] = a2.y;
        }

        // ======== fc(h2[t]) on idle lane 12 of each group ========
        if (sub == 12) {
            ull acc = fpack(fcb, 0.0f);
#pragma unroll
            for (int i = 0; i < 6; ++i)
                acc = ffma2(H2[i], *(const ull*)&s_fcw[2 * i], acc);
            out[(size_t)batch * SEQ + t] = f2sum(acc);
        }

        gc = gn;
    }
}

extern "C" void kernel_launch(void* const* d_in, const int* in_sizes, int n_in,
                              void* d_out, int out_size) {
    const float* x     = (const float*)d_in[0];
    const float* w_ih0 = (const float*)d_in[1];
    const float* w_hh0 = (const float*)d_in[2];
    const float* b_ih0 = (const float*)d_in[3];
    const float* b_hh0 = (const float*)d_in[4];
    const float* w_ih1 = (const float*)d_in[5];
    const float* w_hh1 = (const float*)d_in[6];
    const float* b_ih1 = (const float*)d_in[7];
    const float* b_hh1 = (const float*)d_in[8];
    const float* fc_w  = (const float*)d_in[9];
    const float* fc_b  = (const float*)d_in[10];
    float* out = (float*)d_out;

    gi0_kernel<<<(int)(NROWS / GI_ROWS), 128>>>(x, w_ih0, b_ih0);
    gru_scan_kernel<<<S_GRID, S_THREADS>>>(w_hh0, b_hh0, w_ih1, w_hh1,
                                           b_ih1, b_hh1, fc_w, fc_b, out);
}

// round 14
// speedup vs baseline: 1.1493x; 1.1493x over previous
#include <cuda_runtime.h>

// GRU_67714454389230: 2-layer GRU (H=12, IN=18) + fc(12->1), B=4096, T=512.
// Round 14: FUSED single kernel. Evidence (R7 vs R13): the scan has a ~1200
// cyc/iteration floor independent of per-warp work -> extra instructions are
// nearly free. So each block computes gi0 for ITS OWN 4 batches as a prologue
// (~15-20us, no cross-block dependency), then runs the measured-best scan
// config (R7: 2 groups x 2 batches, ALL weights in regs, plane-float4 gi,
// R8 layer pipelining, R9 r/z pre-scale). Eliminates the 93us gi0 kernel.

static constexpr int IN_DIM = 18;
static constexpr int HID    = 12;
static constexpr int BATCH  = 4096;
static constexpr int SEQ    = 512;
static constexpr size_t NROWS = (size_t)BATCH * SEQ;   // 2,097,152

typedef unsigned long long ull;

// plane layout: g_gi0[u*NROWS + (b*SEQ+t)] = float4(0.5*gi_r, 0.5*gi_z, gi_n, 0)
__device__ float4 g_gi0[HID * NROWS];

// ---------------- helpers ----------------
__device__ __forceinline__ ull ffma2(ull a, ull b, ull c) {
    ull d;
    asm("fma.rn.f32x2 %0, %1, %2, %3;" : "=l"(d) : "l"(a), "l"(b), "l"(c));
    return d;
}
__device__ __forceinline__ float f2sum(ull v) {
    float lo, hi;
    asm("mov.b64 {%0, %1}, %2;" : "=f"(lo), "=f"(hi) : "l"(v));
    return lo + hi;
}
__device__ __forceinline__ ull fpack(float lo, float hi) {
    ull v;
    asm("mov.b64 %0, {%1, %2};" : "=l"(v) : "f"(lo), "f"(hi));
    return v;
}
__device__ __forceinline__ float tanhapx(float x) {
    float y;
    asm("tanh.approx.f32 %0, %1;" : "=f"(y) : "f"(x));
    return y;
}
// input is ALREADY 0.5*(pre-activation)
__device__ __forceinline__ float sig_pre(float half_x) {
    return fmaf(tanhapx(half_x), 0.5f, 0.5f);
}

// ---------------- fused kernel ----------------
// 1024 blocks x 32 threads. Block W owns batches 4W..4W+3.
// Phase 1: gi0 for those 4 batches (2048 rows) -> plane scratch.
// Phase 2: R7-config recurrent scan over the same 4 batches.
static constexpr int S_GRID = BATCH / 4;   // 1024

__global__ __launch_bounds__(32, 8)
void gru_fused_kernel(const float* __restrict__ x,
                      const float* __restrict__ w_ih0, const float* __restrict__ b_ih0,
                      const float* __restrict__ w_hh0, const float* __restrict__ b_hh0,
                      const float* __restrict__ w_ih1, const float* __restrict__ w_hh1,
                      const float* __restrict__ b_ih1, const float* __restrict__ b_hh1,
                      const float* __restrict__ fc_w, const float* __restrict__ fc_b,
                      float* __restrict__ out)
{
    __shared__ ull   s_w[36][9];            // w_ih0 pairs (r,z pre-scaled)
    __shared__ float s_b[36];
    __shared__ ull   s_x[64 * 9];           // 64 x-rows staging
    __shared__ __align__(16) float s_h1[2][2][HID];   // [group][batch][unit]
    __shared__ __align__(16) float s_h2[2][2][HID];
    __shared__ float s_fcw[HID];

    const int lane = threadIdx.x;
    const int W    = blockIdx.x;

    // ================= Phase 1: gi0 for batches 4W..4W+3 =================
    for (int i = lane; i < 36 * 9; i += 32) {
        const int j = i / 9, k = i % 9;
        const float sc = (j < 24) ? 0.5f : 1.0f;
        const float* wp = w_ih0 + j * IN_DIM + 2 * k;
        s_w[j][k] = fpack(wp[0] * sc, wp[1] * sc);
    }
    if (lane > 27) { /* nothing */ }
    for (int i = lane; i < 36; i += 32)
        s_b[i] = b_ih0[i] * ((i < 24) ? 0.5f : 1.0f);

    const size_t R0 = (size_t)W * 2048;                 // first row of block
    const ull* xg = (const ull*)(x + R0 * IN_DIM);      // 2048 rows x 9 ull

#pragma unroll 1
    for (int c = 0; c < 32; ++c) {          // 32 chunks x 64 rows
        __syncthreads();
        for (int i = lane; i < 64 * 9; i += 32) s_x[i] = xg[(size_t)c * 576 + i];
        __syncthreads();

        ull xr0[9], xr1[9];                 // rows lane, lane+32 of chunk
#pragma unroll
        for (int k = 0; k < 9; ++k) {
            xr0[k] = s_x[lane * 9 + k];
            xr1[k] = s_x[(lane + 32) * 9 + k];
        }
#pragma unroll
        for (int u2 = 0; u2 < HID; ++u2) {
            float r0g[3], r1g[3];
#pragma unroll
            for (int g = 0; g < 3; ++g) {
                const int j = g * HID + u2;
                ull a0 = fpack(s_b[j], 0.0f);
                ull a1 = a0;
#pragma unroll
                for (int k = 0; k < 9; ++k) {
                    const ull wv = s_w[j][k];
                    a0 = ffma2(xr0[k], wv, a0);
                    a1 = ffma2(xr1[k], wv, a1);
                }
                r0g[g] = f2sum(a0); r1g[g] = f2sum(a1);
            }
            float4* pl = g_gi0 + (size_t)u2 * NROWS + R0 + (size_t)c * 64;
            pl[lane]      = make_float4(r0g[0], r0g[1], r0g[2], 0.0f);
            pl[lane + 32] = make_float4(r1g[0], r1g[1], r1g[2], 0.0f);
        }
    }
    __syncthreads();    // global writes visible block-wide before the scan

    // ================= Phase 2: recurrent scan (R7 config) =================
    const int grp_l = lane >> 4;
    const int sub   = lane & 15;
    const int u     = (sub < HID) ? sub : HID - 1;
    const int bA    = 4 * W + 2 * grp_l;
    const int bB    = bA + 1;

    if (lane < HID) s_fcw[lane] = fc_w[lane];

    // ALL recurrent weights in registers (f32x2 pairs); r,z rows scaled 0.5.
    ull whh0[3][6], wih1[3][6], whh1[3][6];
#pragma unroll
    for (int g = 0; g < 3; ++g) {
        const float s = (g < 2) ? 0.5f : 1.0f;
        const float* p0 = w_hh0 + (g * HID + u) * HID;
        const float* p1 = w_ih1 + (g * HID + u) * HID;
        const float* p2 = w_hh1 + (g * HID + u) * HID;
#pragma unroll
        for (int i = 0; i < 6; ++i) {
            whh0[g][i] = fpack(p0[2*i] * s, p0[2*i+1] * s);
            wih1[g][i] = fpack(p1[2*i] * s, p1[2*i+1] * s);
            whh1[g][i] = fpack(p2[2*i] * s, p2[2*i+1] * s);
        }
    }

    const float bh0r = b_hh0[u] * 0.5f;
    const float bh0z = b_hh0[HID + u] * 0.5f;
    const float bh0n = b_hh0[2 * HID + u];
    const ull pbh0n = fpack(bh0n, 0.0f);
    const ull pb2r  = fpack((b_ih1[u]       + b_hh1[u])       * 0.5f, 0.0f);
    const ull pb2z  = fpack((b_ih1[HID + u] + b_hh1[HID + u]) * 0.5f, 0.0f);
    const ull pb2in = fpack(b_ih1[2 * HID + u], 0.0f);
    const ull pb2hn = fpack(b_hh1[2 * HID + u], 0.0f);
    const float fcb = fc_b[0];

    // plane gi pointers: per-lane contiguous stream (16B/step, L1-hit heavy)
    const float4* gpA = g_gi0 + (size_t)u * NROWS + (size_t)bA * SEQ;
    const float4* gpB = g_gi0 + (size_t)u * NROWS + (size_t)bB * SEQ;

    ull H1A[6], H1B[6], H2A[6], H2B[6];
#pragma unroll
    for (int i = 0; i < 6; ++i) { H1A[i] = H1B[i] = H2A[i] = H2B[i] = 0ull; }
    float hp1A, hp1B, hp2A = 0.0f, hp2B = 0.0f;
    __syncthreads();

    // ---- prologue: h1[0] = GRU1(gi0[0], 0) ----
    {
        const float4 gA = gpA[0], gB = gpB[0];
        const float rA = sig_pre(gA.x + bh0r);
        const float rB = sig_pre(gB.x + bh0r);
        const float zA = sig_pre(gA.y + bh0z);
        const float zB = sig_pre(gB.y + bh0z);
        const float nA = tanhapx(fmaf(rA, bh0n, gA.z));
        const float nB = tanhapx(fmaf(rB, bh0n, gB.z));
        hp1A = nA - zA * nA;
        hp1B = nB - zB * nB;
        if (sub < HID) { s_h1[grp_l][0][u] = hp1A; s_h1[grp_l][1][u] = hp1B; }
        __syncwarp();
        const ulonglong2* pa = (const ulonglong2*)s_h1[grp_l][0];
        const ulonglong2* pb = (const ulonglong2*)s_h1[grp_l][1];
        const ulonglong2 a0 = pa[0], a1 = pa[1], a2 = pa[2];
        const ulonglong2 b0 = pb[0], b1 = pb[1], b2 = pb[2];
        H1A[0] = a0.x; H1A[1] = a0.y; H1A[2] = a1.x;
        H1A[3] = a1.y; H1A[4] = a2.x; H1A[5] = a2.y;
        H1B[0] = b0.x; H1B[1] = b0.y; H1B[2] = b1.x;
        H1B[3] = b1.y; H1B[4] = b2.x; H1B[5] = b2.y;
    }

    float4 gA = gpA[1], gB = gpB[1];   // gi for t+1 = 1

#pragma unroll 1
    for (int t = 0; t < SEQ; ++t) {
        const int tn = (t + 2 < SEQ) ? (t + 2) : SEQ - 1;
        const float4 gA_n = gpA[tn];
        const float4 gB_n = gpB[tn];

        // ======== layer 2 @ t (H1=h1[t], H2=h2[t-1])  +  layer 1 @ t+1 ========
        ull prA = pb2r, pzA = pb2z, pnA = pb2hn, piA = pb2in;
        ull prB = pb2r, pzB = pb2z, pnB = pb2hn, piB = pb2in;
        ull qrA = fpack(gA.x, bh0r), qzA = fpack(gA.y, bh0z), qnA = pbh0n;
        ull qrB = fpack(gB.x, bh0r), qzB = fpack(gB.y, bh0z), qnB = pbh0n;

#pragma unroll
        for (int i = 0; i < 6; ++i) {
            prA = ffma2(H2A[i], whh1[0][i], prA); prB = ffma2(H2B[i], whh1[0][i], prB);
            pzA = ffma2(H2A[i], whh1[1][i], pzA); pzB = ffma2(H2B[i], whh1[1][i], pzB);
            pnA = ffma2(H2A[i], whh1[2][i], pnA); pnB = ffma2(H2B[i], whh1[2][i], pnB);
            prA = ffma2(H1A[i], wih1[0][i], prA); prB = ffma2(H1B[i], wih1[0][i], prB);
            pzA = ffma2(H1A[i], wih1[1][i], pzA); pzB = ffma2(H1B[i], wih1[1][i], pzB);
            piA = ffma2(H1A[i], wih1[2][i], piA); piB = ffma2(H1B[i], wih1[2][i], piB);
            qrA = ffma2(H1A[i], whh0[0][i], qrA); qrB = ffma2(H1B[i], whh0[0][i], qrB);
            qzA = ffma2(H1A[i], whh0[1][i], qzA); qzB = ffma2(H1B[i], whh0[1][i], qzB);
            qnA = ffma2(H1A[i], whh0[2][i], qnA); qnB = ffma2(H1B[i], whh0[2][i], qnB);
        }

        // layer2 activations -> h2[t]
        const float r2A = sig_pre(f2sum(prA));
        const float r2B = sig_pre(f2sum(prB));
        const float z2A = sig_pre(f2sum(pzA));
        const float z2B = sig_pre(f2sum(pzB));
        const float n2A = tanhapx(fmaf(r2A, f2sum(pnA), f2sum(piA)));
        const float n2B = tanhapx(fmaf(r2B, f2sum(pnB), f2sum(piB)));
        const float hn2A = fmaf(z2A, hp2A - n2A, n2A);
        const float hn2B = fmaf(z2B, hp2B - n2B, n2B);
        hp2A = hn2A; hp2B = hn2B;

        // layer1 activations -> h1[t+1]
        const float r1A = sig_pre(f2sum(qrA));
        const float r1B = sig_pre(f2sum(qrB));
        const float z1A = sig_pre(f2sum(qzA));
        const float z1B = sig_pre(f2sum(qzB));
        const float n1A = tanhapx(fmaf(r1A, f2sum(qnA), gA.z));
        const float n1B = tanhapx(fmaf(r1B, f2sum(qnB), gB.z));
        const float hn1A = fmaf(z1A, hp1A - n1A, n1A);
        const float hn1B = fmaf(z1B, hp1B - n1B, n1B);
        hp1A = hn1A; hp1B = hn1B;

        // ======== combined exchange ========
        if (sub < HID) {
            s_h1[grp_l][0][u] = hn1A; s_h1[grp_l][1][u] = hn1B;
            s_h2[grp_l][0][u] = hn2A; s_h2[grp_l][1][u] = hn2B;
        }
        __syncwarp();
        {
            const ulonglong2* pa = (const ulonglong2*)s_h1[grp_l][0];
            const ulonglong2* pb = (const ulonglong2*)s_h1[grp_l][1];
            const ulonglong2 a0 = pa[0], a1 = pa[1], a2 = pa[2];
            const ulonglong2 b0 = pb[0], b1 = pb[1], b2 = pb[2];
            H1A[0] = a0.x; H1A[1] = a0.y; H1A[2] = a1.x;
            H1A[3] = a1.y; H1A[4] = a2.x; H1A[5] = a2.y;
            H1B[0] = b0.x; H1B[1] = b0.y; H1B[2] = b1.x;
            H1B[3] = b1.y; H1B[4] = b2.x; H1B[5] = b2.y;
        }
        {
            const ulonglong2* pa = (const ulonglong2*)s_h2[grp_l][0];
            const ulonglong2* pb = (const ulonglong2*)s_h2[grp_l][1];
            const ulonglong2 a0 = pa[0], a1 = pa[1], a2 = pa[2];
            const ulonglong2 b0 = pb[0], b1 = pb[1], b2 = pb[2];
            H2A[0] = a0.x; H2A[1] = a0.y; H2A[2] = a1.x;
            H2A[3] = a1.y; H2A[4] = a2.x; H2A[5] = a2.y;
            H2B[0] = b0.x; H2B[1] = b0.y; H2B[2] = b1.x;
            H2B[3] = b1.y; H2B[4] = b2.x; H2B[5] = b2.y;
        }

        // ======== fc(h2[t]) on idle lanes 12 (A) / 13 (B) ========
        if (sub >= 12 && sub < 14) {
            const ull* hh = (sub == 12) ? H2A : H2B;
            ull acc = fpack(fcb, 0.0f);
#pragma unroll
            for (int i = 0; i < 6; ++i)
                acc = ffma2(hh[i], *(const ull*)&s_fcw[2 * i], acc);
            out[(size_t)((sub == 12) ? bA : bB) * SEQ + t] = f2sum(acc);
        }

        gA = gA_n; gB = gB_n;
    }
}

extern "C" void kernel_launch(void* const* d_in, const int* in_sizes, int n_in,
                              void* d_out, int out_size) {
    const float* x     = (const float*)d_in[0];
    const float* w_ih0 = (const float*)d_in[1];
    const float* w_hh0 = (const float*)d_in[2];
    const float* b_ih0 = (const float*)d_in[3];
    const float* b_hh0 = (const float*)d_in[4];
    const float* w_ih1 = (const float*)d_in[5];
    const float* w_hh1 = (const float*)d_in[6];
    const float* b_ih1 = (const float*)d_in[7];
    const float* b_hh1 = (const float*)d_in[8];
    const float* fc_w  = (const float*)d_in[9];
    const float* fc_b  = (const float*)d_in[10];
    float* out = (float*)d_out;

    gru_fused_kernel<<<S_GRID, 32>>>(x, w_ih0, b_ih0, w_hh0, b_hh0,
                                     w_ih1, w_hh1, b_ih1, b_hh1,
                                     fc_w, fc_b, out);
}